// round 4
// baseline (speedup 1.0000x reference)
#include <cuda_runtime.h>

// e3LayerNorm over irreps 128x0e+64x1o+32x2e, graph-segmented (batch sorted).
// out[i,c] = a[g,c]*x[i,c] + b[g,c]; a/b fold mean-subtract, inv-std (scalar
// cols), weight, bias.
//
// Schedule: 8 groups of 8 contiguous graphs. In launch k EVERY CTA does both
// a stats slice of group k (DRAM read, warms L2) and a norm slice of group
// k-1 (L2 read + DRAM write) -> identical work per CTA, no tail. Phase order
// alternates by CTA parity so DRAM read and write streams mix continuously.
// norm(k-1) consumes stats finished in launch k-1 -> no intra-launch dep.
// Thread layout: 480 threads = 120 float4 columns x 4 row lanes.

#define NTOT     480
#define NC4      120
#define NSCAL    128
#define NB       64
#define GSZ      8
#define NGROUPS  (NB / GSZ)
#define THREADS  480
#define GRID_FUSED 432          // 54 CTAs per graph; 3 CTAs/SM (444 slots)
#define CPG      (GRID_FUSED / GSZ)
#define EPSV     1e-5f

__device__ int   g_start[NB + 1];
__device__ float g_sum[NB][NTOT];
__device__ float g_sumsq[NB][NSCAL];

__global__ void prep_kernel() {
    int i = blockIdx.x * blockDim.x + threadIdx.x;
    if (i < NB * NTOT)  ((float*)g_sum)[i]   = 0.f;
    if (i < NB * NSCAL) ((float*)g_sumsq)[i] = 0.f;
}

// g_start[g] = lower_bound(batch, g); handles int64 or int32 batch (probe an
// odd int32 word near the end: int64 high word == 0, int32 value ~63).
__global__ void bounds_kernel(const void* __restrict__ batch_raw, int N) {
    int t = threadIdx.x;
    if (t > NB) return;
    const int* b32 = (const int*)batch_raw;
    const long long* b64 = (const long long*)batch_raw;
    int probe = (N & 1) ? (N - 2) : (N - 1);
    bool is64 = (b32[probe] < 32);
    int lo = 0, hi = N;
    while (lo < hi) {
        int mid = (lo + hi) >> 1;
        long long v = is64 ? b64[mid] : (long long)b32[mid];
        if (v < (long long)t) lo = mid + 1; else hi = mid;
    }
    g_start[t] = lo;
}

__device__ __forceinline__ void slice(int G, int sub, int& r0, int& r1) {
    int gs0 = g_start[G], gs1 = g_start[G + 1];
    long long len = (long long)(gs1 - gs0);
    r0 = gs0 + (int)(len * sub / CPG);
    r1 = gs0 + (int)(len * (sub + 1) / CPG);
}

__device__ __forceinline__ void acc4(float4& a, float4& q, const float4 v, bool sc) {
    a.x += v.x; a.y += v.y; a.z += v.z; a.w += v.w;
    if (sc) {
        q.x = fmaf(v.x, v.x, q.x); q.y = fmaf(v.y, v.y, q.y);
        q.z = fmaf(v.z, v.z, q.z); q.w = fmaf(v.w, v.w, q.w);
    }
}

__device__ void do_stats(const float4* __restrict__ x4, int group, int idx) {
    __shared__ float4 s_s[4][NC4];
    __shared__ float4 s_q[4][32];

    int t = threadIdx.x, lc = t % NC4, lr = t / NC4;
    int G = group * GSZ + idx / CPG;
    int r0, r1; slice(G, idx % CPG, r0, r1);

    float4 a0 = {0,0,0,0}, a1 = {0,0,0,0};
    float4 q0 = {0,0,0,0}, q1 = {0,0,0,0};
    bool sc = (lc < 32);

    int r = r0 + lr;
    for (; r + 12 < r1; r += 16) {
        int i0 = r * NC4 + lc;
        float4 v0 = x4[i0];
        float4 v1 = x4[i0 + 4 * NC4];
        float4 v2 = x4[i0 + 8 * NC4];
        float4 v3 = x4[i0 + 12 * NC4];
        acc4(a0, q0, v0, sc); acc4(a1, q1, v1, sc);
        acc4(a0, q0, v2, sc); acc4(a1, q1, v3, sc);
    }
    for (; r < r1; r += 4)
        acc4(a0, q0, x4[r * NC4 + lc], sc);

    a0.x += a1.x; a0.y += a1.y; a0.z += a1.z; a0.w += a1.w;
    q0.x += q1.x; q0.y += q1.y; q0.z += q1.z; q0.w += q1.w;

    s_s[lr][lc] = a0;
    if (sc) s_q[lr][lc] = q0;
    __syncthreads();
    if (lr == 0) {
        float4 t0 = s_s[0][lc], t1 = s_s[1][lc], t2 = s_s[2][lc], t3 = s_s[3][lc];
        atomicAdd(&g_sum[G][lc*4+0], t0.x + t1.x + t2.x + t3.x);
        atomicAdd(&g_sum[G][lc*4+1], t0.y + t1.y + t2.y + t3.y);
        atomicAdd(&g_sum[G][lc*4+2], t0.z + t1.z + t2.z + t3.z);
        atomicAdd(&g_sum[G][lc*4+3], t0.w + t1.w + t2.w + t3.w);
        if (sc) {
            float4 u0 = s_q[0][lc], u1 = s_q[1][lc], u2 = s_q[2][lc], u3 = s_q[3][lc];
            atomicAdd(&g_sumsq[G][lc*4+0], u0.x + u1.x + u2.x + u3.x);
            atomicAdd(&g_sumsq[G][lc*4+1], u0.y + u1.y + u2.y + u3.y);
            atomicAdd(&g_sumsq[G][lc*4+2], u0.z + u1.z + u2.z + u3.z);
            atomicAdd(&g_sumsq[G][lc*4+3], u0.w + u1.w + u2.w + u3.w);
        }
    }
    __syncthreads();   // s_s/s_q reusable; keep phases cleanly separated
}

__device__ __forceinline__ int ch_of(int c) {
    return (c < NSCAL) ? c : (c < 320 ? 128 + (c - 128) / 3
                                      : 192 + (c - 320) / 5);
}

__device__ __forceinline__ float4 fma4(const float4 v, const float4 a, const float4 b) {
    float4 o;
    o.x = fmaf(v.x, a.x, b.x); o.y = fmaf(v.y, a.y, b.y);
    o.z = fmaf(v.z, a.z, b.z); o.w = fmaf(v.w, a.w, b.w);
    return o;
}

__device__ void do_norm(const float4* __restrict__ x4,
                        const float* __restrict__ weight,
                        const float* __restrict__ bias,
                        float4* __restrict__ o4, int group, int idx) {
    __shared__ float s_norm;

    int t = threadIdx.x, lc = t % NC4, lr = t / NC4;
    int G = group * GSZ + idx / CPG;
    int r0, r1; slice(G, idx % CPG, r0, r1);

    float inv_d = 1.0f / ((float)(g_start[G + 1] - g_start[G]) + 1e-12f);

    const float4* gsum4 = (const float4*)g_sum[G];
    float4 s4 = gsum4[lc];
    float4 mean4;
    mean4.x = s4.x * inv_d; mean4.y = s4.y * inv_d;
    mean4.z = s4.z * inv_d; mean4.w = s4.w * inv_d;

    if (t < 32) {
        const float4* gsq4 = (const float4*)g_sumsq[G];
        float4 q = gsq4[t];
        float v = (q.x * inv_d - mean4.x * mean4.x)
                + (q.y * inv_d - mean4.y * mean4.y)
                + (q.z * inv_d - mean4.z * mean4.z)
                + (q.w * inv_d - mean4.w * mean4.w);
        #pragma unroll
        for (int off = 16; off > 0; off >>= 1)
            v += __shfl_xor_sync(0xffffffffu, v, off);
        if (t == 0) s_norm = v * (1.0f / NSCAL);
    }
    __syncthreads();
    float inv = 1.0f / (sqrtf(s_norm) + EPSV);

    float4 a4, b4;
    {
        float* mp = (float*)&mean4;
        float* ap = (float*)&a4;
        float* bp = (float*)&b4;
        #pragma unroll
        for (int k = 0; k < 4; ++k) {
            int c = lc * 4 + k;
            float w = weight[ch_of(c)];
            if (c < NSCAL) { ap[k] = w * inv; bp[k] = bias[c] - mp[k] * ap[k]; }
            else           { ap[k] = w;       bp[k] = -mp[k] * w; }
        }
    }

    int r = r0 + lr;
    for (; r + 12 < r1; r += 16) {
        int i0 = r * NC4 + lc;
        float4 v0 = __ldcs(&x4[i0]);
        float4 v1 = __ldcs(&x4[i0 + 4 * NC4]);
        float4 v2 = __ldcs(&x4[i0 + 8 * NC4]);
        float4 v3 = __ldcs(&x4[i0 + 12 * NC4]);
        __stcs(&o4[i0],            fma4(v0, a4, b4));
        __stcs(&o4[i0 + 4 * NC4],  fma4(v1, a4, b4));
        __stcs(&o4[i0 + 8 * NC4],  fma4(v2, a4, b4));
        __stcs(&o4[i0 + 12 * NC4], fma4(v3, a4, b4));
    }
    for (; r < r1; r += 4) {
        int i0 = r * NC4 + lc;
        __stcs(&o4[i0], fma4(__ldcs(&x4[i0]), a4, b4));
    }
    __syncthreads();
}

// Every CTA runs BOTH roles (identical work -> no imbalance). Phase order
// alternates by CTA parity to mix DRAM read and write streams.
__global__ __launch_bounds__(THREADS) void fused_kernel(
    const float4* __restrict__ x4,
    const float* __restrict__ weight,
    const float* __restrict__ bias,
    float4* __restrict__ o4,
    int normGroup, int statsGroup)
{
    int idx = blockIdx.x;
    if (idx & 1) {
        if (normGroup  >= 0) do_norm(x4, weight, bias, o4, normGroup, idx);
        if (statsGroup >= 0) do_stats(x4, statsGroup, idx);
    } else {
        if (statsGroup >= 0) do_stats(x4, statsGroup, idx);
        if (normGroup  >= 0) do_norm(x4, weight, bias, o4, normGroup, idx);
    }
}

extern "C" void kernel_launch(void* const* d_in, const int* in_sizes, int n_in,
                              void* d_out, int out_size) {
    const float4* x4    = (const float4*)d_in[0];
    const float* weight = (const float*)d_in[1];
    const float* bias   = (const float*)d_in[2];
    const void*  batch  = d_in[3];
    int N = in_sizes[0] / NTOT;

    prep_kernel<<<(NB * NTOT + 255) / 256, 256>>>();
    bounds_kernel<<<1, 128>>>(batch, N);

    float4* o4 = (float4*)d_out;
    fused_kernel<<<GRID_FUSED, THREADS>>>(x4, weight, bias, o4, -1, 0);
    for (int p = 0; p < NGROUPS - 1; ++p)
        fused_kernel<<<GRID_FUSED, THREADS>>>(x4, weight, bias, o4, p, p + 1);
    fused_kernel<<<GRID_FUSED, THREADS>>>(x4, weight, bias, o4, NGROUPS - 1, -1);
}